// round 13
// baseline (speedup 1.0000x reference)
#include <cuda_runtime.h>
#include <cuda_fp16.h>
#include <cstdint>
#include <cstring>

namespace {
constexpr int T_STEPS = 512;
constexpr int TILE_B  = 16;
constexpr int THREADS = 384;             // 4 L1 warps + 8 L2 warps
constexpr int GRID    = 2048 / TILE_B;

constexpr int OFF_A1  = 0;               // 64 frags * 512B
constexpr int OFF_A2  = 32768;           // 128 frags * 512B
constexpr int OFF_HH  = 98304;           // 2 parity buffers * 4352 B
constexpr int HBUF    = 4352;            // 16 rows * HS fp16
constexpr int OFF_X   = 98304 + 2 * HBUF;
constexpr int SMEM_TOTAL = OFF_X + 4096; // 111104 B
constexpr int HS = 136;                  // fp16 elems per h row (conflict-free pad)

__device__ __forceinline__ uint32_t smem_u32(const void* p) {
  uint32_t a;
  asm("{ .reg .u64 t; cvta.to.shared.u64 t, %1; cvt.u32.u64 %0, t; }" : "=r"(a) : "l"(p));
  return a;
}
__device__ __forceinline__ void ldm4(uint32_t* r, uint32_t a) {
  asm volatile("ldmatrix.sync.aligned.m8n8.x4.shared.b16 {%0,%1,%2,%3}, [%4];"
               : "=r"(r[0]), "=r"(r[1]), "=r"(r[2]), "=r"(r[3]) : "r"(a));
}
__device__ __forceinline__ void mma_hf(float4& d, const uint4& a, uint32_t b0, uint32_t b1) {
  asm volatile("mma.sync.aligned.m16n8k16.row.col.f32.f16.f16.f32 "
               "{%0,%1,%2,%3}, {%4,%5,%6,%7}, {%8,%9}, {%0,%1,%2,%3};"
               : "+f"(d.x), "+f"(d.y), "+f"(d.z), "+f"(d.w)
               : "r"(a.x), "r"(a.y), "r"(a.z), "r"(a.w), "r"(b0), "r"(b1));
}
__device__ __forceinline__ uint32_t pkhf2(float lo, float hi) {
  __half l = __float2half_rn(lo), h = __float2half_rn(hi);
  unsigned short ls, hs;
  memcpy(&ls, &l, 2); memcpy(&hs, &h, 2);
  return (uint32_t)ls | ((uint32_t)hs << 16);
}
__device__ __forceinline__ float tanh_ap(float x) {
  float y; asm("tanh.approx.f32 %0, %1;" : "=f"(y) : "f"(x)); return y;
}
__device__ __forceinline__ float sig_ap(float x) {
  return fmaf(tanh_ap(0.5f * x), 0.5f, 0.5f);
}
}  // namespace

__global__ void __launch_bounds__(THREADS, 1) lstm2_ws_kernel(
    const float* __restrict__ x,
    const float* __restrict__ Wih0, const float* __restrict__ Whh0,
    const float* __restrict__ bih0, const float* __restrict__ bhh0,
    const float* __restrict__ Wih1, const float* __restrict__ Whh1,
    const float* __restrict__ bih1, const float* __restrict__ bhh1,
    const float* __restrict__ fcW,  const float* __restrict__ fcb,
    float* __restrict__ out)
{
  extern __shared__ char sm[];
  const uint32_t sb = smem_u32(sm);
  const int tid = threadIdx.x, w = tid >> 5, lane = tid & 31;
  const int bBase = blockIdx.x * TILE_B;
  const bool isL1 = (w < 4);
  const int wsL1 = w;        // 0..3   (L1: M-tiles 4w..4w+3)
  const int wsL2 = w - 4;    // 0..7   (L2: M-tiles 2ws..2ws+1)
  const int p_ = lane >> 2, cquad = lane & 3;

  // ---- build A fragments in smem (per-lane mma layout, fp16), row perm:
  // tile T, row R = 16T + p + 8q -> gate g=(R&31)>>3, unit u=(R>>5)*8+(R&7)
  for (int i = tid; i < 64 * 32; i += THREADS) {
    int f = i >> 5, l = i & 31;
    int mt = f >> 2, kc = f & 3;
    int lp = l >> 2, c0 = (l & 3) * 2;
    float wv[8];
#pragma unroll
    for (int e = 0; e < 8; ++e) {
      int R = mt * 16 + lp + ((e >> 1) & 1) * 8;
      int k = kc * 16 + c0 + (e & 1) + (e >> 2) * 8;
      int g = (R & 31) >> 3, u = (R >> 5) * 8 + (R & 7);
      wv[e] = Whh0[(g * 64 + u) * 64 + k];
    }
    *(uint4*)(sm + OFF_A1 + (size_t)i * 16) =
        make_uint4(pkhf2(wv[0],wv[1]), pkhf2(wv[2],wv[3]),
                   pkhf2(wv[4],wv[5]), pkhf2(wv[6],wv[7]));
  }
  for (int i = tid; i < 128 * 32; i += THREADS) {
    int f = i >> 5, l = i & 31;
    int mt = f >> 3, kc = f & 7;
    int lp = l >> 2, c0 = (l & 3) * 2;
    float wv[8];
#pragma unroll
    for (int e = 0; e < 8; ++e) {
      int R = mt * 16 + lp + ((e >> 1) & 1) * 8;
      int k = kc * 16 + c0 + (e & 1) + (e >> 2) * 8;
      int g = (R & 31) >> 3, u = (R >> 5) * 8 + (R & 7);
      wv[e] = (k < 64) ? Wih1[(g * 64 + u) * 64 + k]
                       : Whh1[(g * 64 + u) * 64 + (k - 64)];
    }
    *(uint4*)(sm + OFF_A2 + (size_t)i * 16) =
        make_uint4(pkhf2(wv[0],wv[1]), pkhf2(wv[2],wv[3]),
                   pkhf2(wv[4],wv[5]), pkhf2(wv[6],wv[7]));
  }
  // zero both h parity buffers
  for (int i = tid; i < 2 * HBUF / 4; i += THREADS)
    reinterpret_cast<uint32_t*>(sm + OFF_HH)[i] = 0u;

  // per-thread activation constants
  float wxx[2][4], bb0[2][4], bb1[4];
  if (isL1) {
#pragma unroll
    for (int us = 0; us < 2; ++us) {
      int u = 16 * wsL1 + 8 * us + p_;
#pragma unroll
      for (int g = 0; g < 4; ++g) {
        wxx[us][g] = Wih0[g * 64 + u];
        bb0[us][g] = bih0[g * 64 + u] + bhh0[g * 64 + u];
      }
    }
  } else {
    int u = 8 * wsL2 + p_;
#pragma unroll
    for (int g = 0; g < 4; ++g)
      bb1[g] = bih1[g * 64 + u] + bhh1[g * 64 + u];
  }

  // ldmatrix per-lane offset: tile ti: n=((ti>>1)&1)*8+(lane&7), k=(ti&1)*8
  const int ti = lane >> 3;
  const uint32_t boff2 =
      (uint32_t)((((ti >> 1) & 1) * 8 + (lane & 7)) * HS + (ti & 1) * 8) * 2;

  float* xb = reinterpret_cast<float*>(sm + OFF_X);
  float cst[8];
#pragma unroll
  for (int q = 0; q < 8; ++q) cst[q] = 0.f;

  __syncthreads();

  // ---- unified resident A fragments: L1 -> a1 (4mt x 4kc), L2 -> a2 (2mt x 8kc)
  uint4 aRes[16];
  if (isL1) {
#pragma unroll
    for (int mt = 0; mt < 4; ++mt)
#pragma unroll
      for (int kc = 0; kc < 4; ++kc)
        aRes[mt*4+kc] = *(const uint4*)(sm + OFF_A1 +
            (size_t)((((4*wsL1+mt)*4 + kc)*32) + lane) * 16);
  } else {
#pragma unroll
    for (int mt = 0; mt < 2; ++mt)
#pragma unroll
      for (int kc = 0; kc < 8; ++kc)
        aRes[mt*8+kc] = *(const uint4*)(sm + OFF_A2 +
            (size_t)((((2*wsL2+mt)*8 + kc)*32) + lane) * 16);
  }

  // ===== pipelined phase loop: L1 computes h1(ph), L2 computes h2(ph-1) =====
  for (int ph = 0; ph <= T_STEPS; ++ph) {
    const int p = ph & 1;
    if ((ph & 63) == 0 && ph < T_STEPS) {
      if (tid < 256) {
        int b16 = tid >> 4, tq = tid & 15;
        float4 v = *reinterpret_cast<const float4*>(
            x + (size_t)(bBase + b16) * T_STEPS + ph + tq * 4);
        xb[(tq * 4 + 0) * 16 + b16] = v.x;
        xb[(tq * 4 + 1) * 16 + b16] = v.y;
        xb[(tq * 4 + 2) * 16 + b16] = v.z;
        xb[(tq * 4 + 3) * 16 + b16] = v.w;
      }
      __syncthreads();
    }
    const uint32_t rdA = sb + OFF_HH + (uint32_t)(p ^ 1) * HBUF;  // h1(ph-1)
    const uint32_t rdB = sb + OFF_HH + (uint32_t)p * HBUF;        // h2(ph-2)

    if (isL1) {
      if (ph < T_STEPS) {
        uint32_t Bf[4][4];
#pragma unroll
        for (int kc = 0; kc < 4; ++kc) ldm4(Bf[kc], rdA + boff2 + kc * 32);
        float4 Da[4][2];
#pragma unroll
        for (int mt = 0; mt < 4; ++mt)
#pragma unroll
          for (int nt = 0; nt < 2; ++nt) Da[mt][nt] = make_float4(0.f,0.f,0.f,0.f);
#pragma unroll
        for (int kc = 0; kc < 4; ++kc)
#pragma unroll
          for (int mt = 0; mt < 4; ++mt)
#pragma unroll
            for (int nt = 0; nt < 2; ++nt)
              mma_hf(Da[mt][nt], aRes[mt*4+kc], Bf[kc][nt*2], Bf[kc][nt*2+1]);

        // act1: thread owns units 16w+8us+p_, batches nt*8+cquad*2+jj
        float xv[4];
#pragma unroll
        for (int q = 0; q < 4; ++q)
          xv[q] = xb[(ph & 63) * 16 + (q >> 1) * 8 + cquad * 2 + (q & 1)];
#pragma unroll
        for (int us = 0; us < 2; ++us) {
          int u = 16 * wsL1 + 8 * us + p_;
#pragma unroll
          for (int nt = 0; nt < 2; ++nt)
#pragma unroll
            for (int jj = 0; jj < 2; ++jj) {
              int n = nt * 8 + cquad * 2 + jj;
              int q = nt * 2 + jj;
              float gi = (jj ? Da[2*us][nt].y   : Da[2*us][nt].x)   + bb0[us][0] + wxx[us][0]*xv[q];
              float gf = (jj ? Da[2*us][nt].w   : Da[2*us][nt].z)   + bb0[us][1] + wxx[us][1]*xv[q];
              float gg = (jj ? Da[2*us+1][nt].y : Da[2*us+1][nt].x) + bb0[us][2] + wxx[us][2]*xv[q];
              float go = (jj ? Da[2*us+1][nt].w : Da[2*us+1][nt].z) + bb0[us][3] + wxx[us][3]*xv[q];
              float cn = sig_ap(gf) * cst[us*4+q] + sig_ap(gi) * tanh_ap(gg);
              cst[us*4+q] = cn;
              float h = sig_ap(go) * tanh_ap(cn);
              *(__half*)(sm + OFF_HH + (size_t)p * HBUF + (size_t)(n * HS + u) * 2) =
                  __float2half_rn(h);
            }
        }
      }
    } else {
      if (ph >= 1) {
        uint32_t Bf[8][4];
#pragma unroll
        for (int kc = 0; kc < 4; ++kc) ldm4(Bf[kc], rdA + boff2 + kc * 32);
#pragma unroll
        for (int kc = 0; kc < 4; ++kc) ldm4(Bf[4+kc], rdB + boff2 + 128 + kc * 32);
        float4 Da[2][2];
#pragma unroll
        for (int mt = 0; mt < 2; ++mt)
#pragma unroll
          for (int nt = 0; nt < 2; ++nt) Da[mt][nt] = make_float4(0.f,0.f,0.f,0.f);
#pragma unroll
        for (int kc = 0; kc < 8; ++kc)
#pragma unroll
          for (int mt = 0; mt < 2; ++mt)
#pragma unroll
            for (int nt = 0; nt < 2; ++nt)
              mma_hf(Da[mt][nt], aRes[mt*8+kc], Bf[kc][nt*2], Bf[kc][nt*2+1]);

        // act2: unit 8*wsL2+p_, batches nt*8+cquad*2+jj; writes h2(ph-1)
        int u = 8 * wsL2 + p_;
#pragma unroll
        for (int nt = 0; nt < 2; ++nt)
#pragma unroll
          for (int jj = 0; jj < 2; ++jj) {
            int n = nt * 8 + cquad * 2 + jj;
            int q = nt * 2 + jj;
            float gi = (jj ? Da[0][nt].y : Da[0][nt].x) + bb1[0];
            float gf = (jj ? Da[0][nt].w : Da[0][nt].z) + bb1[1];
            float gg = (jj ? Da[1][nt].y : Da[1][nt].x) + bb1[2];
            float go = (jj ? Da[1][nt].w : Da[1][nt].z) + bb1[3];
            float cn = sig_ap(gf) * cst[q] + sig_ap(gi) * tanh_ap(gg);
            cst[q] = cn;
            float h = sig_ap(go) * tanh_ap(cn);
            *(__half*)(sm + OFF_HH + (size_t)(p ^ 1) * HBUF +
                       (size_t)(n * HS + 64 + u) * 2) = __float2half_rn(h);
            if (ph == T_STEPS) xb[u * 16 + n] = h;   // exact fp32 h2(T-1) for FC
          }
      }
    }
    __syncthreads();   // single phase barrier: all writes -> next-phase readers
  }

  // ===== FC epilogue: out[b] = fcW . h2(T-1) + fcb (exact fp32) =====
  if (tid < TILE_B) {
    float acc = fcb[0];
#pragma unroll 8
    for (int u = 0; u < 64; ++u)
      acc += fcW[u] * xb[u * 16 + tid];
    out[bBase + tid] = acc;
  }
}

extern "C" void kernel_launch(void* const* d_in, const int* in_sizes, int n_in,
                              void* d_out, int out_size) {
  (void)in_sizes; (void)n_in; (void)out_size;
  cudaFuncSetAttribute(lstm2_ws_kernel,
                       cudaFuncAttributeMaxDynamicSharedMemorySize, SMEM_TOTAL);
  lstm2_ws_kernel<<<GRID, THREADS, SMEM_TOTAL>>>(
      (const float*)d_in[0],
      (const float*)d_in[1], (const float*)d_in[2],
      (const float*)d_in[3], (const float*)d_in[4],
      (const float*)d_in[5], (const float*)d_in[6],
      (const float*)d_in[7], (const float*)d_in[8],
      (const float*)d_in[9], (const float*)d_in[10],
      (float*)d_out);
}

// round 14
// speedup vs baseline: 1.0002x; 1.0002x over previous
#include <cuda_runtime.h>
#include <cuda_fp16.h>
#include <cstdint>
#include <cstring>

namespace {
constexpr int T_STEPS = 512;
constexpr int TILE_B  = 16;
constexpr int THREADS = 384;             // 4 L1 warps + 8 L2 warps
constexpr int GRID    = 2048 / TILE_B;

constexpr int OFF_A1  = 0;               // 64 frags * 512B
constexpr int OFF_A2  = 32768;           // 128 frags * 512B
constexpr int OFF_HH  = 98304;           // 2 parity buffers * 4352 B
constexpr int HBUF    = 4352;            // 16 rows * HS fp16
constexpr int OFF_X   = 98304 + 2 * HBUF;
constexpr int SMEM_TOTAL = OFF_X + 4096; // 111104 B
constexpr int HS = 136;                  // fp16 elems per h row (conflict-free pad)

__device__ __forceinline__ uint32_t smem_u32(const void* p) {
  uint32_t a;
  asm("{ .reg .u64 t; cvta.to.shared.u64 t, %1; cvt.u32.u64 %0, t; }" : "=r"(a) : "l"(p));
  return a;
}
__device__ __forceinline__ void ldm4(uint32_t* r, uint32_t a) {
  asm volatile("ldmatrix.sync.aligned.m8n8.x4.shared.b16 {%0,%1,%2,%3}, [%4];"
               : "=r"(r[0]), "=r"(r[1]), "=r"(r[2]), "=r"(r[3]) : "r"(a));
}
__device__ __forceinline__ void mma_hf(float4& d, const uint4& a, uint32_t b0, uint32_t b1) {
  asm volatile("mma.sync.aligned.m16n8k16.row.col.f32.f16.f16.f32 "
               "{%0,%1,%2,%3}, {%4,%5,%6,%7}, {%8,%9}, {%0,%1,%2,%3};"
               : "+f"(d.x), "+f"(d.y), "+f"(d.z), "+f"(d.w)
               : "r"(a.x), "r"(a.y), "r"(a.z), "r"(a.w), "r"(b0), "r"(b1));
}
__device__ __forceinline__ uint32_t pkhf2(float lo, float hi) {
  __half l = __float2half_rn(lo), h = __float2half_rn(hi);
  unsigned short ls, hs;
  memcpy(&ls, &l, 2); memcpy(&hs, &h, 2);
  return (uint32_t)ls | ((uint32_t)hs << 16);
}
__device__ __forceinline__ float tanh_ap(float x) {
  float y; asm("tanh.approx.f32 %0, %1;" : "=f"(y) : "f"(x)); return y;
}
__device__ __forceinline__ float sig_ap(float x) {
  return fmaf(tanh_ap(0.5f * x), 0.5f, 0.5f);
}
}  // namespace

__global__ void __launch_bounds__(THREADS, 1) lstm2_ws_kernel(
    const float* __restrict__ x,
    const float* __restrict__ Wih0, const float* __restrict__ Whh0,
    const float* __restrict__ bih0, const float* __restrict__ bhh0,
    const float* __restrict__ Wih1, const float* __restrict__ Whh1,
    const float* __restrict__ bih1, const float* __restrict__ bhh1,
    const float* __restrict__ fcW,  const float* __restrict__ fcb,
    float* __restrict__ out)
{
  extern __shared__ char sm[];
  const uint32_t sb = smem_u32(sm);
  const int tid = threadIdx.x, w = tid >> 5, lane = tid & 31;
  const int bBase = blockIdx.x * TILE_B;
  const bool isL1 = (w < 4);
  const int wsL1 = w;        // 0..3   (L1: M-tiles 4w..4w+3)
  const int wsL2 = w - 4;    // 0..7   (L2: M-tiles 2ws..2ws+1)
  const int p_ = lane >> 2, cquad = lane & 3;

  // ---- build A fragments in smem (per-lane mma layout, fp16), row perm:
  // tile T, row R = 16T + p + 8q -> gate g=(R&31)>>3, unit u=(R>>5)*8+(R&7)
  for (int i = tid; i < 64 * 32; i += THREADS) {
    int f = i >> 5, l = i & 31;
    int mt = f >> 2, kc = f & 3;
    int lp = l >> 2, c0 = (l & 3) * 2;
    float wv[8];
#pragma unroll
    for (int e = 0; e < 8; ++e) {
      int R = mt * 16 + lp + ((e >> 1) & 1) * 8;
      int k = kc * 16 + c0 + (e & 1) + (e >> 2) * 8;
      int g = (R & 31) >> 3, u = (R >> 5) * 8 + (R & 7);
      wv[e] = Whh0[(g * 64 + u) * 64 + k];
    }
    *(uint4*)(sm + OFF_A1 + (size_t)i * 16) =
        make_uint4(pkhf2(wv[0],wv[1]), pkhf2(wv[2],wv[3]),
                   pkhf2(wv[4],wv[5]), pkhf2(wv[6],wv[7]));
  }
  for (int i = tid; i < 128 * 32; i += THREADS) {
    int f = i >> 5, l = i & 31;
    int mt = f >> 3, kc = f & 7;
    int lp = l >> 2, c0 = (l & 3) * 2;
    float wv[8];
#pragma unroll
    for (int e = 0; e < 8; ++e) {
      int R = mt * 16 + lp + ((e >> 1) & 1) * 8;
      int k = kc * 16 + c0 + (e & 1) + (e >> 2) * 8;
      int g = (R & 31) >> 3, u = (R >> 5) * 8 + (R & 7);
      wv[e] = (k < 64) ? Wih1[(g * 64 + u) * 64 + k]
                       : Whh1[(g * 64 + u) * 64 + (k - 64)];
    }
    *(uint4*)(sm + OFF_A2 + (size_t)i * 16) =
        make_uint4(pkhf2(wv[0],wv[1]), pkhf2(wv[2],wv[3]),
                   pkhf2(wv[4],wv[5]), pkhf2(wv[6],wv[7]));
  }
  // zero both h parity buffers
  for (int i = tid; i < 2 * HBUF / 4; i += THREADS)
    reinterpret_cast<uint32_t*>(sm + OFF_HH)[i] = 0u;

  // per-thread activation constants
  float wxx[2][4], bb0[2][4], bb1[4];
  if (isL1) {
#pragma unroll
    for (int us = 0; us < 2; ++us) {
      int u = 16 * wsL1 + 8 * us + p_;
#pragma unroll
      for (int g = 0; g < 4; ++g) {
        wxx[us][g] = Wih0[g * 64 + u];
        bb0[us][g] = bih0[g * 64 + u] + bhh0[g * 64 + u];
      }
    }
  } else {
    int u = 8 * wsL2 + p_;
#pragma unroll
    for (int g = 0; g < 4; ++g)
      bb1[g] = bih1[g * 64 + u] + bhh1[g * 64 + u];
  }

  // ldmatrix per-lane offset: tile ti: n=((ti>>1)&1)*8+(lane&7), k=(ti&1)*8
  const int ti = lane >> 3;
  const uint32_t boff2 =
      (uint32_t)((((ti >> 1) & 1) * 8 + (lane & 7)) * HS + (ti & 1) * 8) * 2;

  float* xb = reinterpret_cast<float*>(sm + OFF_X);
  float cst[8];
#pragma unroll
  for (int q = 0; q < 8; ++q) cst[q] = 0.f;

  __syncthreads();

  // ---- unified resident A fragments: L1 -> a1 (4mt x 4kc), L2 -> a2 (2mt x 8kc)
  uint4 aRes[16];
  if (isL1) {
#pragma unroll
    for (int mt = 0; mt < 4; ++mt)
#pragma unroll
      for (int kc = 0; kc < 4; ++kc)
        aRes[mt*4+kc] = *(const uint4*)(sm + OFF_A1 +
            (size_t)((((4*wsL1+mt)*4 + kc)*32) + lane) * 16);
  } else {
#pragma unroll
    for (int mt = 0; mt < 2; ++mt)
#pragma unroll
      for (int kc = 0; kc < 8; ++kc)
        aRes[mt*8+kc] = *(const uint4*)(sm + OFF_A2 +
            (size_t)((((2*wsL2+mt)*8 + kc)*32) + lane) * 16);
  }

  // ===== pipelined phase loop: L1 computes h1(ph), L2 computes h2(ph-1) =====
  for (int ph = 0; ph <= T_STEPS; ++ph) {
    const int p = ph & 1;
    if ((ph & 63) == 0 && ph < T_STEPS) {
      if (tid < 256) {
        int b16 = tid >> 4, tq = tid & 15;
        float4 v = *reinterpret_cast<const float4*>(
            x + (size_t)(bBase + b16) * T_STEPS + ph + tq * 4);
        xb[(tq * 4 + 0) * 16 + b16] = v.x;
        xb[(tq * 4 + 1) * 16 + b16] = v.y;
        xb[(tq * 4 + 2) * 16 + b16] = v.z;
        xb[(tq * 4 + 3) * 16 + b16] = v.w;
      }
      __syncthreads();
    }
    const uint32_t rdA = sb + OFF_HH + (uint32_t)(p ^ 1) * HBUF;  // h1(ph-1)
    const uint32_t rdB = sb + OFF_HH + (uint32_t)p * HBUF;        // h2(ph-2)

    if (isL1) {
      if (ph < T_STEPS) {
        uint32_t Bf[4][4];
#pragma unroll
        for (int kc = 0; kc < 4; ++kc) ldm4(Bf[kc], rdA + boff2 + kc * 32);
        float4 Da[4][2];
#pragma unroll
        for (int mt = 0; mt < 4; ++mt)
#pragma unroll
          for (int nt = 0; nt < 2; ++nt) Da[mt][nt] = make_float4(0.f,0.f,0.f,0.f);
#pragma unroll
        for (int kc = 0; kc < 4; ++kc)
#pragma unroll
          for (int mt = 0; mt < 4; ++mt)
#pragma unroll
            for (int nt = 0; nt < 2; ++nt)
              mma_hf(Da[mt][nt], aRes[mt*4+kc], Bf[kc][nt*2], Bf[kc][nt*2+1]);

        // act1: thread owns units 16w+8us+p_, batches nt*8+cquad*2+jj
        float xv[4];
#pragma unroll
        for (int q = 0; q < 4; ++q)
          xv[q] = xb[(ph & 63) * 16 + (q >> 1) * 8 + cquad * 2 + (q & 1)];
#pragma unroll
        for (int us = 0; us < 2; ++us) {
          int u = 16 * wsL1 + 8 * us + p_;
#pragma unroll
          for (int nt = 0; nt < 2; ++nt)
#pragma unroll
            for (int jj = 0; jj < 2; ++jj) {
              int n = nt * 8 + cquad * 2 + jj;
              int q = nt * 2 + jj;
              float gi = (jj ? Da[2*us][nt].y   : Da[2*us][nt].x)   + bb0[us][0] + wxx[us][0]*xv[q];
              float gf = (jj ? Da[2*us][nt].w   : Da[2*us][nt].z)   + bb0[us][1] + wxx[us][1]*xv[q];
              float gg = (jj ? Da[2*us+1][nt].y : Da[2*us+1][nt].x) + bb0[us][2] + wxx[us][2]*xv[q];
              float go = (jj ? Da[2*us+1][nt].w : Da[2*us+1][nt].z) + bb0[us][3] + wxx[us][3]*xv[q];
              float cn = sig_ap(gf) * cst[us*4+q] + sig_ap(gi) * tanh_ap(gg);
              cst[us*4+q] = cn;
              float h = sig_ap(go) * tanh_ap(cn);
              *(__half*)(sm + OFF_HH + (size_t)p * HBUF + (size_t)(n * HS + u) * 2) =
                  __float2half_rn(h);
            }
        }
      }
    } else {
      if (ph >= 1) {
        uint32_t Bf[8][4];
#pragma unroll
        for (int kc = 0; kc < 4; ++kc) ldm4(Bf[kc], rdA + boff2 + kc * 32);
#pragma unroll
        for (int kc = 0; kc < 4; ++kc) ldm4(Bf[4+kc], rdB + boff2 + 128 + kc * 32);
        float4 Da[2][2];
#pragma unroll
        for (int mt = 0; mt < 2; ++mt)
#pragma unroll
          for (int nt = 0; nt < 2; ++nt) Da[mt][nt] = make_float4(0.f,0.f,0.f,0.f);
#pragma unroll
        for (int kc = 0; kc < 8; ++kc)
#pragma unroll
          for (int mt = 0; mt < 2; ++mt)
#pragma unroll
            for (int nt = 0; nt < 2; ++nt)
              mma_hf(Da[mt][nt], aRes[mt*8+kc], Bf[kc][nt*2], Bf[kc][nt*2+1]);

        // act2: unit 8*wsL2+p_, batches nt*8+cquad*2+jj; writes h2(ph-1)
        int u = 8 * wsL2 + p_;
#pragma unroll
        for (int nt = 0; nt < 2; ++nt)
#pragma unroll
          for (int jj = 0; jj < 2; ++jj) {
            int n = nt * 8 + cquad * 2 + jj;
            int q = nt * 2 + jj;
            float gi = (jj ? Da[0][nt].y : Da[0][nt].x) + bb1[0];
            float gf = (jj ? Da[0][nt].w : Da[0][nt].z) + bb1[1];
            float gg = (jj ? Da[1][nt].y : Da[1][nt].x) + bb1[2];
            float go = (jj ? Da[1][nt].w : Da[1][nt].z) + bb1[3];
            float cn = sig_ap(gf) * cst[q] + sig_ap(gi) * tanh_ap(gg);
            cst[q] = cn;
            float h = sig_ap(go) * tanh_ap(cn);
            *(__half*)(sm + OFF_HH + (size_t)(p ^ 1) * HBUF +
                       (size_t)(n * HS + 64 + u) * 2) = __float2half_rn(h);
            if (ph == T_STEPS) xb[u * 16 + n] = h;   // exact fp32 h2(T-1) for FC
          }
      }
    }
    __syncthreads();   // single phase barrier: all writes -> next-phase readers
  }

  // ===== FC epilogue: out[b] = fcW . h2(T-1) + fcb (exact fp32) =====
  if (tid < TILE_B) {
    float acc = fcb[0];
#pragma unroll 8
    for (int u = 0; u < 64; ++u)
      acc += fcW[u] * xb[u * 16 + tid];
    out[bBase + tid] = acc;
  }
}

extern "C" void kernel_launch(void* const* d_in, const int* in_sizes, int n_in,
                              void* d_out, int out_size) {
  (void)in_sizes; (void)n_in; (void)out_size;
  cudaFuncSetAttribute(lstm2_ws_kernel,
                       cudaFuncAttributeMaxDynamicSharedMemorySize, SMEM_TOTAL);
  lstm2_ws_kernel<<<GRID, THREADS, SMEM_TOTAL>>>(
      (const float*)d_in[0],
      (const float*)d_in[1], (const float*)d_in[2],
      (const float*)d_in[3], (const float*)d_in[4],
      (const float*)d_in[5], (const float*)d_in[6],
      (const float*)d_in[7], (const float*)d_in[8],
      (const float*)d_in[9], (const float*)d_in[10],
      (float*)d_out);
}